// round 13
// baseline (speedup 1.0000x reference)
#include <cuda_runtime.h>
#include <cstdint>

// Problem shape
#define BB      16
#define TT      4096
#define UU      1024
#define TC      8                  // t-rows per chunk (halved: more, smaller blocks)
#define RR      2                  // rows held in registers
#define SR      6                  // rows via cp.async into smem (column-private)
#define NC      (TT / TC)          // 512 chunks per batch chain
#define U4      (UU / 4)           // 256 float4 per row
#define THREADS 256                // one thread per float4 column
#define NTICK   (BB * NC)          // 8192 chunk tickets
#define FACTOR  0.5f

// Decoupled-lookback scratch (device globals: no allocation allowed).
__device__ float4 g_agg[NTICK * U4];            // 32 MiB
__device__ float4 g_inc[NTICK * U4];            // 32 MiB
// Flags: 0 = invalid, 1 = aggregate ready, 2 = inclusive ready.
// Last slot doubles as the dynamic-ticket counter. Reset by memset each launch.
__device__ unsigned int g_flags[NTICK + 1];

__device__ __forceinline__ void st_release_gpu(unsigned int* p, unsigned int v) {
    asm volatile("st.release.gpu.u32 [%0], %1;" :: "l"(p), "r"(v) : "memory");
}
__device__ __forceinline__ unsigned int ld_acquire_gpu(const unsigned int* p) {
    unsigned int v;
    asm volatile("ld.acquire.gpu.u32 %0, [%1];" : "=r"(v) : "l"(p) : "memory");
    return v;
}
__device__ __forceinline__ void cp_async16(uint32_t saddr, const void* gaddr) {
    asm volatile("cp.async.cg.shared.global [%0], [%1], 16;" :: "r"(saddr), "l"(gaddr));
}

__global__ __launch_bounds__(THREADS, 6)
void rac_scan_kernel(const float4* __restrict__ xv,
                     const float4* __restrict__ h0v,
                     float4* __restrict__ outv) {
    __shared__ float4 s_tile[SR * THREADS];   // 24 KB, column-private per thread
    __shared__ unsigned int s_vb;
    __shared__ int s_D;
    __shared__ int s_done;

    const int tid = threadIdx.x;

    // Dynamic ticket: chain order == scheduling order (no deadlock).
    if (tid == 0) s_vb = atomicAdd(&g_flags[NTICK], 1u);
    __syncthreads();
    const unsigned int vb = s_vb;
    const int b = vb & (BB - 1);   // batch fastest -> all 16 chains advance together
    const int c = vb >> 4;         // chunk index along the chain (0..511)

    const unsigned base = ((unsigned)b * TT + (unsigned)c * TC) * U4 + tid;

    // Rows RR..TC-1 -> smem via cp.async (no register cost, deep MLP).
    const uint32_t sbase = (uint32_t)__cvta_generic_to_shared(&s_tile[tid]);
#pragma unroll
    for (int t = 0; t < SR; t++)
        cp_async16(sbase + t * (THREADS * 16),
                   (const void*)(xv + base + (unsigned)(RR + t) * U4));
    asm volatile("cp.async.commit_group;" ::: "memory");

    const float4 h = h0v[b * U4 + tid];

    // Rows 0..RR-1 -> registers (streamed), prefixed.
    float4 v[RR];
#pragma unroll
    for (int t = 0; t < RR; t++) v[t] = __ldcs(&xv[base + (unsigned)t * U4]);
#pragma unroll
    for (int t = 1; t < RR; t++) {
        v[t].x += v[t - 1].x;
        v[t].y += v[t - 1].y;
        v[t].z += v[t - 1].z;
        v[t].w += v[t - 1].w;
    }

    const int chain = b * NC;
    const int sidx  = (chain + c) * U4 + tid;
    const bool is_last = (c == NC - 1);
    float4 excl = make_float4(0.f, 0.f, 0.f, 0.f);

    // ---- Pre-phase lookback: overlapped with the cp.async flight. ----
    // Non-blocking: breaks as soon as a poll round shows no progress.
    int base_p = c - 1;
    bool done = (c == 0);
    while (!done) {
        if (tid < 32) {
            const int p = base_p - tid;
            const unsigned f = (p >= 0) ? ld_acquire_gpu(&g_flags[chain + p]) : 0u;
            const unsigned b1 = __ballot_sync(0xffffffffu, f >= 1u);
            const unsigned b2 = __ballot_sync(0xffffffffu, f == 2u);
            if (tid == 0) {
                const int k = __ffs(~b1);                 // first not-ready lane (+1)
                const int nready = (k == 0) ? 32 : (k - 1);
                const int l2 = __ffs(b2) - 1;             // nearest inclusive; -1 if none
                if (l2 >= 0 && l2 <= nready) { s_done = 1; s_D = l2; }
                else                         { s_done = 0; s_D = nready; }
            }
        }
        __syncthreads();
        const int D = s_D;
        const int fin = s_done;
        if (!fin && D == 0) break;       // no progress yet -> go back to our load
        for (int l = 0; l < D; l++) {
            const float4 a = __ldcg(&g_agg[(chain + base_p - l) * U4 + tid]);
            excl.x += a.x; excl.y += a.y; excl.z += a.z; excl.w += a.w;
        }
        if (fin) {
            const float4 a = __ldcg(&g_inc[(chain + base_p - D) * U4 + tid]);
            excl.x += a.x; excl.y += a.y; excl.z += a.z; excl.w += a.w;
            done = true;
            break;
        }
        base_p -= D;
        __syncthreads();                 // protect s_D/s_done before next poll
    }

    // ---- Wait for data; local prefix over smem rows (column-private, no sync). ----
    asm volatile("cp.async.wait_group 0;" ::: "memory");
    float4 run = make_float4(0.f, 0.f, 0.f, 0.f);
#pragma unroll
    for (int t = 0; t < SR; t++) {
        const float4 a = s_tile[t * THREADS + tid];
        run.x += a.x; run.y += a.y; run.z += a.z; run.w += a.w;
        s_tile[t * THREADS + tid] = run;
    }
    float4 agg;
    agg.x = v[RR - 1].x + run.x;
    agg.y = v[RR - 1].y + run.y;
    agg.z = v[RR - 1].z + run.z;
    agg.w = v[RR - 1].w + run.w;

    if (done) {
        // Lookback resolved during the load: single publish, inclusive directly.
        if (!is_last) {
            float4 inc;
            inc.x = excl.x + agg.x; inc.y = excl.y + agg.y;
            inc.z = excl.z + agg.z; inc.w = excl.w + agg.w;
            g_inc[sidx] = inc;
            __syncthreads();             // all data stores happen-before the release
            if (tid == 0) st_release_gpu(&g_flags[chain + c], 2u);
        }
    } else {
        // Publish aggregate so successors can make progress immediately.
        g_agg[sidx] = agg;
        __syncthreads();                 // HB for all threads' stores; also protects s_D
        if (tid == 0) st_release_gpu(&g_flags[chain + c], 1u);

        // ---- Residual lookback (blocking, same windowed protocol). ----
        for (;;) {
            if (tid < 32) {
                const int p = base_p - tid;
                const unsigned f = (p >= 0) ? ld_acquire_gpu(&g_flags[chain + p]) : 0u;
                const unsigned b1 = __ballot_sync(0xffffffffu, f >= 1u);
                const unsigned b2 = __ballot_sync(0xffffffffu, f == 2u);
                if (tid == 0) {
                    const int k = __ffs(~b1);
                    const int nready = (k == 0) ? 32 : (k - 1);
                    const int l2 = __ffs(b2) - 1;
                    if (l2 >= 0 && l2 <= nready) { s_done = 1; s_D = l2; }
                    else                         { s_done = 0; s_D = nready; }
                }
            }
            __syncthreads();
            const int D = s_D;
            const int fin = s_done;
            for (int l = 0; l < D; l++) {
                const float4 a = __ldcg(&g_agg[(chain + base_p - l) * U4 + tid]);
                excl.x += a.x; excl.y += a.y; excl.z += a.z; excl.w += a.w;
            }
            if (fin) {
                const float4 a = __ldcg(&g_inc[(chain + base_p - D) * U4 + tid]);
                excl.x += a.x; excl.y += a.y; excl.z += a.z; excl.w += a.w;
                break;
            }
            base_p -= D;
            __syncthreads();
        }

        // Upgrade to inclusive (flag 1 -> 2).
        if (!is_last) {
            float4 inc;
            inc.x = excl.x + agg.x; inc.y = excl.y + agg.y;
            inc.z = excl.z + agg.z; inc.w = excl.w + agg.w;
            g_inc[sidx] = inc;
            __syncthreads();
            if (tid == 0) st_release_gpu(&g_flags[chain + c], 2u);
        }
    }

    // ---- Epilogue: out = h0 + FACTOR * (exclusive + local_prefix) ----
#pragma unroll
    for (int t = 0; t < RR; t++) {
        float4 o;
        o.x = h.x + FACTOR * (excl.x + v[t].x);
        o.y = h.y + FACTOR * (excl.y + v[t].y);
        o.z = h.z + FACTOR * (excl.z + v[t].z);
        o.w = h.w + FACTOR * (excl.w + v[t].w);
        __stcs(&outv[base + (unsigned)t * U4], o);
    }
    const float4 lo = v[RR - 1];
#pragma unroll
    for (int t = 0; t < SR; t++) {
        const float4 p = s_tile[t * THREADS + tid];
        float4 o;
        o.x = h.x + FACTOR * (excl.x + lo.x + p.x);
        o.y = h.y + FACTOR * (excl.y + lo.y + p.y);
        o.z = h.z + FACTOR * (excl.z + lo.z + p.z);
        o.w = h.w + FACTOR * (excl.w + lo.w + p.w);
        __stcs(&outv[base + (unsigned)(RR + t) * U4], o);
    }
}

extern "C" void kernel_launch(void* const* d_in, const int* in_sizes, int n_in,
                              void* d_out, int out_size) {
    (void)in_sizes; (void)n_in; (void)out_size;
    const float4* xv  = (const float4*)d_in[0];   // x:  (16, 4096, 1024) f32
    const float4* h0v = (const float4*)d_in[1];   // h0: (16, 1024) f32
    float4* outv      = (float4*)d_out;           // out:(16, 4096, 1024) f32

    // Reset flags + ticket every launch (captured as a memset node).
    void* flags_ptr = nullptr;
    cudaGetSymbolAddress(&flags_ptr, g_flags);
    cudaMemsetAsync(flags_ptr, 0, (NTICK + 1) * sizeof(unsigned int), 0);

    rac_scan_kernel<<<NTICK, THREADS>>>(xv, h0v, outv);
}

// round 16
// speedup vs baseline: 1.1250x; 1.1250x over previous
#include <cuda_runtime.h>
#include <cstdint>

// Problem shape
#define BB      16
#define TT      4096
#define UU      1024
#define TC      32                 // t-rows per chunk (two 16-row halves)
#define HALF    16
#define RR      4                  // reg rows per thread (per half)
#define SR      12                 // cp.async smem rows per thread (per half)
#define NC      (TT / TC)          // 128 chunks per batch chain
#define U4      (UU / 4)           // 256 float4 per row
#define COLS    256
#define THREADS 512                // (half h, col) ownership
#define NTICK   (BB * NC)          // 2048 chunk tickets
#define FACTOR  0.5f
// dynamic smem: tile[2*SR*COLS] + h0agg[COLS] + excl[COLS]  (float4 each)
#define TILE_F4 (2 * SR * COLS)
#define SMEM_F4 (TILE_F4 + 2 * COLS)
#define SMEM_BYTES (SMEM_F4 * 16)

// Decoupled-lookback scratch (device globals: no allocation allowed).
__device__ float4 g_agg[NTICK * COLS];          // 8 MiB
__device__ float4 g_inc[NTICK * COLS];          // 8 MiB
// Flags: 0 = invalid, 1 = aggregate ready, 2 = inclusive ready.
// Last slot doubles as the dynamic-ticket counter. Reset by memset each launch.
__device__ unsigned int g_flags[NTICK + 1];

__device__ __forceinline__ void st_release_gpu(unsigned int* p, unsigned int v) {
    asm volatile("st.release.gpu.u32 [%0], %1;" :: "l"(p), "r"(v) : "memory");
}
__device__ __forceinline__ unsigned int ld_acquire_gpu(const unsigned int* p) {
    unsigned int v;
    asm volatile("ld.acquire.gpu.u32 %0, [%1];" : "=r"(v) : "l"(p) : "memory");
    return v;
}
__device__ __forceinline__ void cp_async16(uint32_t saddr, const void* gaddr) {
    asm volatile("cp.async.cg.shared.global [%0], [%1], 16;" :: "r"(saddr), "l"(gaddr));
}

__global__ __launch_bounds__(THREADS, 2)
void rac_scan_kernel(const float4* __restrict__ xv,
                     const float4* __restrict__ h0v,
                     float4* __restrict__ outv) {
    extern __shared__ float4 smem[];
    float4* s_tile = smem;                       // [2*SR][COLS], column-private
    float4* s_h0a  = smem + TILE_F4;             // lower-half aggregate handoff
    float4* s_x    = smem + TILE_F4 + COLS;      // exclusive-prefix handoff
    __shared__ unsigned int s_vb;
    __shared__ int s_D;
    __shared__ int s_done;

    const int tid = threadIdx.x;
    const int col = tid & (COLS - 1);
    const int h   = tid >> 8;                    // 0 = rows 0-15, 1 = rows 16-31

    // Dynamic ticket: chain order == scheduling order (no deadlock).
    if (tid == 0) s_vb = atomicAdd(&g_flags[NTICK], 1u);
    __syncthreads();
    const unsigned int vb = s_vb;
    const int b = vb & (BB - 1);   // batch fastest -> all 16 chains advance together
    const int c = vb >> 4;         // chunk index along the chain (0..127)

    // This thread's first row: chunk base + half offset.
    const unsigned base = ((unsigned)b * TT + (unsigned)(c * TC + h * HALF)) * U4 + col;

    // Rows RR..15 of this half -> smem via cp.async (column-private).
    const uint32_t sb0 = (uint32_t)__cvta_generic_to_shared(&s_tile[h * SR * COLS + col]);
#pragma unroll
    for (int t = 0; t < SR; t++)
        cp_async16(sb0 + t * (COLS * 16),
                   (const void*)(xv + base + (unsigned)(RR + t) * U4));
    asm volatile("cp.async.commit_group;" ::: "memory");

    const float4 hv = h0v[b * U4 + col];

    // Rows 0..RR-1 of this half -> registers (streamed), prefixed.
    float4 v[RR];
#pragma unroll
    for (int t = 0; t < RR; t++) v[t] = __ldcs(&xv[base + (unsigned)t * U4]);
#pragma unroll
    for (int t = 1; t < RR; t++) {
        v[t].x += v[t - 1].x;
        v[t].y += v[t - 1].y;
        v[t].z += v[t - 1].z;
        v[t].w += v[t - 1].w;
    }

    const int chain = b * NC;
    const int sidx  = (chain + c) * COLS + col;
    const bool is_last = (c == NC - 1);
    float4 excl = make_float4(0.f, 0.f, 0.f, 0.f);

    // ---- Pre-phase lookback, overlapped with the cp.async flight. ----
    // Warp 0 polls; lower-half threads (h==0, col==tid) accumulate aggregates.
    // Non-blocking: breaks when a poll round shows no progress.
    int base_p = c - 1;
    bool done = (c == 0);
    while (!done) {
        if (tid < 32) {
            const int p = base_p - tid;
            const unsigned f = (p >= 0) ? ld_acquire_gpu(&g_flags[chain + p]) : 0u;
            const unsigned b1 = __ballot_sync(0xffffffffu, f >= 1u);
            const unsigned b2 = __ballot_sync(0xffffffffu, f == 2u);
            if (tid == 0) {
                const int k = __ffs(~b1);                 // first not-ready lane (+1)
                const int nready = (k == 0) ? 32 : (k - 1);
                const int l2 = __ffs(b2) - 1;             // nearest inclusive; -1 if none
                if (l2 >= 0 && l2 <= nready) { s_done = 1; s_D = l2; }
                else                         { s_done = 0; s_D = nready; }
            }
        }
        __syncthreads();
        const int D = s_D;
        const int fin = s_done;
        if (!fin && D == 0) break;       // no progress yet -> go consume our data
        if (h == 0) {
            for (int l = 0; l < D; l++) {
                const float4 a = __ldcg(&g_agg[(chain + base_p - l) * COLS + col]);
                excl.x += a.x; excl.y += a.y; excl.z += a.z; excl.w += a.w;
            }
            if (fin) {
                const float4 a = __ldcg(&g_inc[(chain + base_p - D) * COLS + col]);
                excl.x += a.x; excl.y += a.y; excl.z += a.z; excl.w += a.w;
            }
        }
        if (fin) { done = true; break; }
        base_p -= D;
        __syncthreads();                 // protect s_D/s_done before next poll
    }

    // ---- Wait for data; local prefix over this half's smem rows. ----
    asm volatile("cp.async.wait_group 0;" ::: "memory");
    float4* myrows = &s_tile[h * SR * COLS + col];
    float4 run = make_float4(0.f, 0.f, 0.f, 0.f);
#pragma unroll
    for (int t = 0; t < SR; t++) {
        const float4 a = myrows[t * COLS];
        run.x += a.x; run.y += a.y; run.z += a.z; run.w += a.w;
        myrows[t * COLS] = run;
    }
    // Half-aggregate = sum of this half's 16 rows.
    float4 hagg;
    hagg.x = v[RR - 1].x + run.x;
    hagg.y = v[RR - 1].y + run.y;
    hagg.z = v[RR - 1].z + run.z;
    hagg.w = v[RR - 1].w + run.w;

    // Hand lower half's aggregate to the upper half.
    if (h == 0) s_h0a[col] = hagg;
    __syncthreads();
    float4 A0 = make_float4(0.f, 0.f, 0.f, 0.f);
    float4 bagg = hagg;                         // h==1: becomes full block agg
    if (h == 1) {
        A0 = s_h0a[col];
        bagg.x += A0.x; bagg.y += A0.y; bagg.z += A0.z; bagg.w += A0.w;
    }

    if (!done) {
        // Publish aggregate (upper half holds the full block aggregate).
        if (!is_last) {
            if (h == 1) g_agg[sidx] = bagg;
            __syncthreads();             // HB: h==1 stores before the release
            if (tid == 0) st_release_gpu(&g_flags[chain + c], 1u);
        }
        // ---- Residual lookback (blocking; h==0 accumulates). ----
        for (;;) {
            if (tid < 32) {
                const int p = base_p - tid;
                const unsigned f = (p >= 0) ? ld_acquire_gpu(&g_flags[chain + p]) : 0u;
                const unsigned b1 = __ballot_sync(0xffffffffu, f >= 1u);
                const unsigned b2 = __ballot_sync(0xffffffffu, f == 2u);
                if (tid == 0) {
                    const int k = __ffs(~b1);
                    const int nready = (k == 0) ? 32 : (k - 1);
                    const int l2 = __ffs(b2) - 1;
                    if (l2 >= 0 && l2 <= nready) { s_done = 1; s_D = l2; }
                    else                         { s_done = 0; s_D = nready; }
                }
            }
            __syncthreads();
            const int D = s_D;
            const int fin = s_done;
            if (h == 0) {
                for (int l = 0; l < D; l++) {
                    const float4 a = __ldcg(&g_agg[(chain + base_p - l) * COLS + col]);
                    excl.x += a.x; excl.y += a.y; excl.z += a.z; excl.w += a.w;
                }
                if (fin) {
                    const float4 a = __ldcg(&g_inc[(chain + base_p - D) * COLS + col]);
                    excl.x += a.x; excl.y += a.y; excl.z += a.z; excl.w += a.w;
                }
            }
            if (fin) break;
            base_p -= D;
            __syncthreads();
        }
    }

    // Share exclusive prefix with the upper half.
    if (h == 0) s_x[col] = excl;
    __syncthreads();
    if (h == 1) excl = s_x[col];

    // Publish inclusive prefix (upper half holds block agg).
    if (!is_last) {
        if (h == 1) {
            float4 inc;
            inc.x = excl.x + bagg.x; inc.y = excl.y + bagg.y;
            inc.z = excl.z + bagg.z; inc.w = excl.w + bagg.w;
            g_inc[sidx] = inc;
        }
        __syncthreads();                 // HB: h==1 stores before the release
        if (tid == 0) st_release_gpu(&g_flags[chain + c], 2u);
    }

    // ---- Epilogue: out = h0 + FACTOR * (excl [+ A0] + local_prefix) ----
    float4 term = excl;
    if (h == 1) { term.x += A0.x; term.y += A0.y; term.z += A0.z; term.w += A0.w; }
#pragma unroll
    for (int t = 0; t < RR; t++) {
        float4 o;
        o.x = hv.x + FACTOR * (term.x + v[t].x);
        o.y = hv.y + FACTOR * (term.y + v[t].y);
        o.z = hv.z + FACTOR * (term.z + v[t].z);
        o.w = hv.w + FACTOR * (term.w + v[t].w);
        __stcs(&outv[base + (unsigned)t * U4], o);
    }
    const float4 lo = v[RR - 1];
#pragma unroll
    for (int t = 0; t < SR; t++) {
        const float4 p = myrows[t * COLS];
        float4 o;
        o.x = hv.x + FACTOR * (term.x + lo.x + p.x);
        o.y = hv.y + FACTOR * (term.y + lo.y + p.y);
        o.z = hv.z + FACTOR * (term.z + lo.z + p.z);
        o.w = hv.w + FACTOR * (term.w + lo.w + p.w);
        __stcs(&outv[base + (unsigned)(RR + t) * U4], o);
    }
}

extern "C" void kernel_launch(void* const* d_in, const int* in_sizes, int n_in,
                              void* d_out, int out_size) {
    (void)in_sizes; (void)n_in; (void)out_size;
    const float4* xv  = (const float4*)d_in[0];   // x:  (16, 4096, 1024) f32
    const float4* h0v = (const float4*)d_in[1];   // h0: (16, 1024) f32
    float4* outv      = (float4*)d_out;           // out:(16, 4096, 1024) f32

    // >48 KB dynamic smem needs an opt-in (host attribute; not an allocation).
    cudaFuncSetAttribute(rac_scan_kernel,
                         cudaFuncAttributeMaxDynamicSharedMemorySize, SMEM_BYTES);

    // Reset flags + ticket every launch (captured as a memset node).
    void* flags_ptr = nullptr;
    cudaGetSymbolAddress(&flags_ptr, g_flags);
    cudaMemsetAsync(flags_ptr, 0, (NTICK + 1) * sizeof(unsigned int), 0);

    rac_scan_kernel<<<NTICK, THREADS, SMEM_BYTES>>>(xv, h0v, outv);
}

// round 17
// speedup vs baseline: 1.2259x; 1.0896x over previous
#include <cuda_runtime.h>
#include <cstdint>

// Problem shape
#define BB      16
#define TT      4096
#define UU      1024
#define TC      16                 // t-rows per chunk
#define RR      4                  // rows held in registers
#define SR      12                 // rows via cp.async into smem (3 groups of 4)
#define GRP     4                  // rows per cp.async commit group
#define NC      (TT / TC)          // 256 chunks per batch chain
#define U4      (UU / 4)           // 256 float4 per row
#define THREADS 256                // one thread per float4 column
#define NTICK   (BB * NC)
#define FACTOR  0.5f

// Decoupled-lookback scratch (device globals: no allocation allowed).
__device__ float4 g_agg[NTICK * U4];            // 16 MiB
__device__ float4 g_inc[NTICK * U4];            // 16 MiB
// Flags: 0 = invalid, 1 = aggregate ready, 2 = inclusive ready.
// Last slot doubles as the dynamic-ticket counter. Reset by memset each launch.
__device__ unsigned int g_flags[NTICK + 1];

__device__ __forceinline__ void st_release_gpu(unsigned int* p, unsigned int v) {
    asm volatile("st.release.gpu.u32 [%0], %1;" :: "l"(p), "r"(v) : "memory");
}
__device__ __forceinline__ unsigned int ld_acquire_gpu(const unsigned int* p) {
    unsigned int v;
    asm volatile("ld.acquire.gpu.u32 %0, [%1];" : "=r"(v) : "l"(p) : "memory");
    return v;
}
__device__ __forceinline__ void cp_async16(uint32_t saddr, const void* gaddr) {
    asm volatile("cp.async.cg.shared.global [%0], [%1], 16;" :: "r"(saddr), "l"(gaddr));
}

__global__ __launch_bounds__(THREADS, 4)
void rac_scan_kernel(const float4* __restrict__ xv,
                     const float4* __restrict__ h0v,
                     float4* __restrict__ outv) {
    __shared__ float4 s_tile[SR * THREADS];   // 48 KB, column-private per thread
    __shared__ unsigned int s_vb;
    __shared__ int s_D[2];
    __shared__ int s_done[2];

    const int tid = threadIdx.x;

    // Dynamic ticket: chain order == scheduling order (no deadlock).
    if (tid == 0) s_vb = atomicAdd(&g_flags[NTICK], 1u);
    __syncthreads();
    const unsigned int vb = s_vb;
    const int b = vb & (BB - 1);   // batch fastest -> all 16 chains advance together
    const int c = vb >> 4;         // chunk index along the chain

    const unsigned base = ((unsigned)b * TT + (unsigned)c * TC) * U4 + tid;

    // Rows RR..15 -> smem via cp.async in 3 commit groups of 4 rows each.
    const uint32_t sbase = (uint32_t)__cvta_generic_to_shared(&s_tile[tid]);
#pragma unroll
    for (int g = 0; g < 3; g++) {
#pragma unroll
        for (int t = 0; t < GRP; t++)
            cp_async16(sbase + (g * GRP + t) * (THREADS * 16),
                       (const void*)(xv + base + (unsigned)(RR + g * GRP + t) * U4));
        asm volatile("cp.async.commit_group;" ::: "memory");
    }

    const float4 h = h0v[b * U4 + tid];

    // Rows 0..RR-1 -> registers (streamed), prefixed.
    float4 v[RR];
#pragma unroll
    for (int t = 0; t < RR; t++) v[t] = __ldcs(&xv[base + (unsigned)t * U4]);
#pragma unroll
    for (int t = 1; t < RR; t++) {
        v[t].x += v[t - 1].x;
        v[t].y += v[t - 1].y;
        v[t].z += v[t - 1].z;
        v[t].w += v[t - 1].w;
    }

    const int chain = b * NC;
    const int sidx  = (chain + c) * U4 + tid;
    const bool is_last = (c == NC - 1);
    float4 excl = make_float4(0.f, 0.f, 0.f, 0.f);

    // ---- Pre-phase lookback, overlapped with the cp.async flight. ----
    // Non-blocking: breaks as soon as a poll round shows no progress.
    int base_p = c - 1;
    int par = 0;
    bool done = (c == 0);
    while (!done) {
        if (tid < 32) {
            const int p = base_p - tid;
            const unsigned f = (p >= 0) ? ld_acquire_gpu(&g_flags[chain + p]) : 0u;
            const unsigned b1 = __ballot_sync(0xffffffffu, f >= 1u);
            const unsigned b2 = __ballot_sync(0xffffffffu, f == 2u);
            if (tid == 0) {
                const int k = __ffs(~b1);                 // first not-ready lane (+1)
                const int nready = (k == 0) ? 32 : (k - 1);
                const int l2 = __ffs(b2) - 1;             // nearest inclusive; -1 if none
                if (l2 >= 0 && l2 <= nready) { s_done[par] = 1; s_D[par] = l2; }
                else                         { s_done[par] = 0; s_D[par] = nready; }
            }
        }
        __syncthreads();                 // publishes s_D[par]; parity protects rewrite
        const int D = s_D[par];
        const int fin = s_done[par];
        par ^= 1;
        if (!fin && D == 0) break;       // no progress yet -> go consume our data
        for (int l = 0; l < D; l++) {
            const float4 a = __ldcg(&g_agg[(chain + base_p - l) * U4 + tid]);
            excl.x += a.x; excl.y += a.y; excl.z += a.z; excl.w += a.w;
        }
        if (fin) {
            const float4 a = __ldcg(&g_inc[(chain + base_p - D) * U4 + tid]);
            excl.x += a.x; excl.y += a.y; excl.z += a.z; excl.w += a.w;
            done = true;
            break;
        }
        base_p -= D;
    }

    // ---- Early stores: if lookback already resolved, rows 0-3 can go now, ----
    // ---- interleaving the write stream with the still-inflight reads.     ----
    if (done) {
#pragma unroll
        for (int t = 0; t < RR; t++) {
            float4 o;
            o.x = h.x + FACTOR * (excl.x + v[t].x);
            o.y = h.y + FACTOR * (excl.y + v[t].y);
            o.z = h.z + FACTOR * (excl.z + v[t].z);
            o.w = h.w + FACTOR * (excl.w + v[t].w);
            __stcs(&outv[base + (unsigned)t * U4], o);
        }
    }

    // ---- Incremental consumption: wait per group, prefix, (store if done). ----
    const float4 lo = v[RR - 1];
    float4 run = make_float4(0.f, 0.f, 0.f, 0.f);
#pragma unroll
    for (int g = 0; g < 3; g++) {
        if (g == 0)      asm volatile("cp.async.wait_group 2;" ::: "memory");
        else if (g == 1) asm volatile("cp.async.wait_group 1;" ::: "memory");
        else             asm volatile("cp.async.wait_group 0;" ::: "memory");
#pragma unroll
        for (int t = 0; t < GRP; t++) {
            const int r = g * GRP + t;
            const float4 a = s_tile[r * THREADS + tid];
            run.x += a.x; run.y += a.y; run.z += a.z; run.w += a.w;
            s_tile[r * THREADS + tid] = run;
        }
        if (done && g < 2) {
            // Store this group's outputs while the next group is in flight.
#pragma unroll
            for (int t = 0; t < GRP; t++) {
                const int r = g * GRP + t;
                const float4 p = s_tile[r * THREADS + tid];
                float4 o;
                o.x = h.x + FACTOR * (excl.x + lo.x + p.x);
                o.y = h.y + FACTOR * (excl.y + lo.y + p.y);
                o.z = h.z + FACTOR * (excl.z + lo.z + p.z);
                o.w = h.w + FACTOR * (excl.w + lo.w + p.w);
                __stcs(&outv[base + (unsigned)(RR + r) * U4], o);
            }
        }
    }
    float4 agg;
    agg.x = lo.x + run.x;
    agg.y = lo.y + run.y;
    agg.z = lo.z + run.z;
    agg.w = lo.w + run.w;

    if (done) {
        // Publish inclusive at the earliest point, then finish last group's stores.
        if (!is_last) {
            float4 inc;
            inc.x = excl.x + agg.x; inc.y = excl.y + agg.y;
            inc.z = excl.z + agg.z; inc.w = excl.w + agg.w;
            g_inc[sidx] = inc;
            __syncthreads();             // all data stores happen-before the release
            if (tid == 0) st_release_gpu(&g_flags[chain + c], 2u);
        }
#pragma unroll
        for (int t = 0; t < GRP; t++) {
            const int r = 2 * GRP + t;
            const float4 p = s_tile[r * THREADS + tid];
            float4 o;
            o.x = h.x + FACTOR * (excl.x + lo.x + p.x);
            o.y = h.y + FACTOR * (excl.y + lo.y + p.y);
            o.z = h.z + FACTOR * (excl.z + lo.z + p.z);
            o.w = h.w + FACTOR * (excl.w + lo.w + p.w);
            __stcs(&outv[base + (unsigned)(RR + r) * U4], o);
        }
    } else {
        // Publish aggregate so successors can make progress immediately.
        g_agg[sidx] = agg;
        __syncthreads();                 // HB for all threads' stores
        if (tid == 0) st_release_gpu(&g_flags[chain + c], 1u);

        // ---- Residual lookback (blocking, same windowed protocol). ----
        for (;;) {
            if (tid < 32) {
                const int p = base_p - tid;
                const unsigned f = (p >= 0) ? ld_acquire_gpu(&g_flags[chain + p]) : 0u;
                const unsigned b1 = __ballot_sync(0xffffffffu, f >= 1u);
                const unsigned b2 = __ballot_sync(0xffffffffu, f == 2u);
                if (tid == 0) {
                    const int k = __ffs(~b1);
                    const int nready = (k == 0) ? 32 : (k - 1);
                    const int l2 = __ffs(b2) - 1;
                    if (l2 >= 0 && l2 <= nready) { s_done[par] = 1; s_D[par] = l2; }
                    else                         { s_done[par] = 0; s_D[par] = nready; }
                }
            }
            __syncthreads();
            const int D = s_D[par];
            const int fin = s_done[par];
            par ^= 1;
            for (int l = 0; l < D; l++) {
                const float4 a = __ldcg(&g_agg[(chain + base_p - l) * U4 + tid]);
                excl.x += a.x; excl.y += a.y; excl.z += a.z; excl.w += a.w;
            }
            if (fin) {
                const float4 a = __ldcg(&g_inc[(chain + base_p - D) * U4 + tid]);
                excl.x += a.x; excl.y += a.y; excl.z += a.z; excl.w += a.w;
                break;
            }
            base_p -= D;
        }

        // Upgrade to inclusive (flag 1 -> 2).
        if (!is_last) {
            float4 inc;
            inc.x = excl.x + agg.x; inc.y = excl.y + agg.y;
            inc.z = excl.z + agg.z; inc.w = excl.w + agg.w;
            g_inc[sidx] = inc;
            __syncthreads();
            if (tid == 0) st_release_gpu(&g_flags[chain + c], 2u);
        }

        // Full epilogue (nothing was stored early on this path).
#pragma unroll
        for (int t = 0; t < RR; t++) {
            float4 o;
            o.x = h.x + FACTOR * (excl.x + v[t].x);
            o.y = h.y + FACTOR * (excl.y + v[t].y);
            o.z = h.z + FACTOR * (excl.z + v[t].z);
            o.w = h.w + FACTOR * (excl.w + v[t].w);
            __stcs(&outv[base + (unsigned)t * U4], o);
        }
#pragma unroll
        for (int r = 0; r < SR; r++) {
            const float4 p = s_tile[r * THREADS + tid];
            float4 o;
            o.x = h.x + FACTOR * (excl.x + lo.x + p.x);
            o.y = h.y + FACTOR * (excl.y + lo.y + p.y);
            o.z = h.z + FACTOR * (excl.z + lo.z + p.z);
            o.w = h.w + FACTOR * (excl.w + lo.w + p.w);
            __stcs(&outv[base + (unsigned)(RR + r) * U4], o);
        }
    }
}

extern "C" void kernel_launch(void* const* d_in, const int* in_sizes, int n_in,
                              void* d_out, int out_size) {
    (void)in_sizes; (void)n_in; (void)out_size;
    const float4* xv  = (const float4*)d_in[0];   // x:  (16, 4096, 1024) f32
    const float4* h0v = (const float4*)d_in[1];   // h0: (16, 1024) f32
    float4* outv      = (float4*)d_out;           // out:(16, 4096, 1024) f32

    // Reset flags + ticket every launch (captured as a memset node).
    void* flags_ptr = nullptr;
    cudaGetSymbolAddress(&flags_ptr, g_flags);
    cudaMemsetAsync(flags_ptr, 0, (NTICK + 1) * sizeof(unsigned int), 0);

    rac_scan_kernel<<<NTICK, THREADS>>>(xv, h0v, outv);
}